// round 1
// baseline (speedup 1.0000x reference)
#include <cuda_runtime.h>
#include <math.h>

#define TTOK 36864   // 4096 batches * 9 spatial

// Scratch (device globals; allocation-free per harness rules)
__device__ float g_big[56623104];   // [1536][T]: rows 0-511 x^T, 512-1023 o3_att, 1024-1535 o7_att
__device__ float g_act[18874368];   // [512][T]: o3^T, then reused for o7^T
__device__ float g_qkv[56623104];   // [1536][T]: q | k | v
__device__ float g_mean[1536];
__device__ float g_var[1536];
__device__ float g_scale[1536];
__device__ float g_shift[1536];

// ---------------------------------------------------------------------------
// x [B, 512, 9] -> g_big rows [0,512) as [C, T], T token = b*9+hw
// ---------------------------------------------------------------------------
__global__ void transpose_in_kernel(const float* __restrict__ x) {
    __shared__ float s[32][296];          // [c][b*9+hw], padded
    int c0 = blockIdx.x * 32;
    int b0 = blockIdx.y * 32;
    int tid = threadIdx.x;                // 0..287 = (c_local*9 + hw)
    const float* xp = x + (size_t)b0 * 4608 + (size_t)c0 * 9;
#pragma unroll 4
    for (int b = 0; b < 32; b++) {
        s[tid / 9][b * 9 + tid % 9] = xp[(size_t)b * 4608 + tid];
    }
    __syncthreads();
#pragma unroll 4
    for (int c = 0; c < 32; c++) {
        g_big[(size_t)(c0 + c) * TTOK + b0 * 9 + tid] = s[c][tid];
    }
}

// ---------------------------------------------------------------------------
// Per-channel mean/var (biased) over a row of g_big
// ---------------------------------------------------------------------------
__global__ void stats_kernel(int rowOff) {
    int c = blockIdx.x + rowOff;
    const float* row = g_big + (size_t)c * TTOK;
    float s = 0.f, q = 0.f;
    for (int t = threadIdx.x; t < TTOK; t += 256) {
        float v = row[t];
        s += v;
        q += v * v;
    }
    __shared__ float rs[256], rq[256];
    rs[threadIdx.x] = s; rq[threadIdx.x] = q;
    __syncthreads();
    for (int o = 128; o > 0; o >>= 1) {
        if (threadIdx.x < o) {
            rs[threadIdx.x] += rs[threadIdx.x + o];
            rq[threadIdx.x] += rq[threadIdx.x + o];
        }
        __syncthreads();
    }
    if (threadIdx.x == 0) {
        float m = rs[0] / (float)TTOK;
        g_mean[c] = m;
        g_var[c]  = rq[0] / (float)TTOK - m * m;
    }
}

// Fold BN (gamma, beta, mean, var) into y = x*scale + shift
__global__ void scaleshift_kernel(const float* __restrict__ gam,
                                  const float* __restrict__ bet, int n) {
    int i = blockIdx.x * blockDim.x + threadIdx.x;
    if (i < n) {
        float inv = rsqrtf(g_var[i] + 1e-5f);
        float sc  = gam[i] * inv;
        g_scale[i] = sc;
        g_shift[i] = bet[i] - g_mean[i] * sc;
    }
}

// ---------------------------------------------------------------------------
// out[m,t] = sum_k act(A[k,t]) * W[m,k] + bias[m]
// act = relu(v*scale[k]+shift[k]) if ACT.  A: [K,T], W: [M,K] row-major.
// 128x128x16 tiles, 256 threads, 8x8 microtile (strided, conflict-free LDS).
// ---------------------------------------------------------------------------
template<bool ACT, bool TRANSOUT>
__global__ __launch_bounds__(256, 2)
void gemm_kernel(const float* __restrict__ A, const float* __restrict__ W,
                 const float* __restrict__ bias, float* __restrict__ out, int K) {
    __shared__ float As[16][128];
    __shared__ float Ws[16][129];
    const int tid = threadIdx.x;
    const int bn = blockIdx.x * 128;
    const int bm = blockIdx.y * 128;
    const int tc = tid & 15;   // column group
    const int tr = tid >> 4;   // row group
    float acc[8][8] = {};

    for (int k0 = 0; k0 < K; k0 += 16) {
#pragma unroll
        for (int i = 0; i < 8; i++) {
            int lin = tid + i * 256;
            int kk = lin >> 7, nn = lin & 127;
            float v = A[(size_t)(k0 + kk) * TTOK + bn + nn];
            if (ACT) v = fmaxf(fmaf(v, g_scale[k0 + kk], g_shift[k0 + kk]), 0.f);
            As[kk][nn] = v;
        }
#pragma unroll
        for (int i = 0; i < 8; i++) {
            int lin = tid + i * 256;
            int mm = lin >> 4, kk = lin & 15;
            Ws[kk][mm] = W[(size_t)(bm + mm) * K + k0 + kk];
        }
        __syncthreads();
#pragma unroll
        for (int kk = 0; kk < 16; kk++) {
            float a[8], w[8];
#pragma unroll
            for (int j = 0; j < 8; j++) a[j] = As[kk][tc + 16 * j];
#pragma unroll
            for (int i = 0; i < 8; i++) w[i] = Ws[kk][tr + 16 * i];
#pragma unroll
            for (int i = 0; i < 8; i++)
#pragma unroll
                for (int j = 0; j < 8; j++)
                    acc[i][j] = fmaf(w[i], a[j], acc[i][j]);
        }
        __syncthreads();
    }

#pragma unroll
    for (int i = 0; i < 8; i++) {
        int m = bm + tr + 16 * i;
        float bv = bias[m];
#pragma unroll
        for (int j = 0; j < 8; j++) {
            int t = bn + tc + 16 * j;
            float v = acc[i][j] + bv;
            if (TRANSOUT) {
                int b = t / 9, hw = t - b * 9;
                out[((size_t)b * 512 + m) * 9 + hw] = v;   // [B, 512, 3, 3]
            } else {
                out[(size_t)m * TTOK + t] = v;
            }
        }
    }
}

// ---------------------------------------------------------------------------
// MHSA core. One block per (batch, head). q/k/v: g_qkv rows [0|512|1024)+h*128.
// L[n,m] = sum_d q[d,n]k[d,m] + pos[d,n]q[d,m]; softmax over m; out = attn @ v^T
// ---------------------------------------------------------------------------
__global__ void attn_kernel(const float* __restrict__ relh,
                            const float* __restrict__ relw, int outRowOff) {
    int b = blockIdx.x >> 2;
    int h = blockIdx.x & 3;
    int d = threadIdx.x;                    // 0..127
    __shared__ float sq[128][9], sk[128][9], sv[128][9], sp[128][9];
    __shared__ float sl[9][9];
    int row = h * 128 + d;
    size_t tb = (size_t)b * 9;
    const float* qp = g_qkv + (size_t)row * TTOK + tb;
    const float* kp = g_qkv + (size_t)(512 + row) * TTOK + tb;
    const float* vp = g_qkv + (size_t)(1024 + row) * TTOK + tb;
#pragma unroll
    for (int m = 0; m < 9; m++) {
        sq[d][m] = qp[m];
        sk[d][m] = kp[m];
        sv[d][m] = vp[m];
    }
    float rw[3], rh[3];
#pragma unroll
    for (int i = 0; i < 3; i++) { rw[i] = relw[row * 3 + i]; rh[i] = relh[row * 3 + i]; }
#pragma unroll
    for (int i = 0; i < 3; i++)
#pragma unroll
        for (int j = 0; j < 3; j++)
            sp[d][i * 3 + j] = rw[i] + rh[j];   // pos[h,d,n], n = i*3+j
    __syncthreads();

    if (d < 81) {
        int n = d / 9, m = d % 9;
        float acc = 0.f;
#pragma unroll 4
        for (int dd = 0; dd < 128; dd++)
            acc += sq[dd][n] * sk[dd][m] + sp[dd][n] * sq[dd][m];
        sl[n][m] = acc;
    }
    __syncthreads();
    if (d < 9) {
        float mx = sl[d][0];
#pragma unroll
        for (int m = 1; m < 9; m++) mx = fmaxf(mx, sl[d][m]);
        float e[9], sum = 0.f;
#pragma unroll
        for (int m = 0; m < 9; m++) { e[m] = __expf(sl[d][m] - mx); sum += e[m]; }
        float inv = 1.f / sum;
#pragma unroll
        for (int m = 0; m < 9; m++) sl[d][m] = e[m] * inv;
    }
    __syncthreads();
    float* op = g_big + (size_t)(outRowOff + row) * TTOK + tb;
#pragma unroll
    for (int n = 0; n < 9; n++) {
        float acc = 0.f;
#pragma unroll
        for (int m = 0; m < 9; m++) acc = fmaf(sv[d][m], sl[n][m], acc);
        op[n] = acc;
    }
}

// ---------------------------------------------------------------------------
extern "C" void kernel_launch(void* const* d_in, const int* in_sizes, int n_in,
                              void* d_out, int out_size) {
    const float* x     = (const float*)d_in[0];
    const float* bn1_g = (const float*)d_in[1];
    const float* bn1_b = (const float*)d_in[2];
    const float* w1    = (const float*)d_in[3];
    const float* b1    = (const float*)d_in[4];
    const float* q_w   = (const float*)d_in[5];
    const float* q_b   = (const float*)d_in[6];
    const float* k_w   = (const float*)d_in[7];
    const float* k_b   = (const float*)d_in[8];
    const float* v_w   = (const float*)d_in[9];
    const float* v_b   = (const float*)d_in[10];
    const float* rel_h = (const float*)d_in[11];
    const float* rel_w = (const float*)d_in[12];
    const float* bn2_g = (const float*)d_in[13];
    const float* bn2_b = (const float*)d_in[14];
    const float* w2    = (const float*)d_in[15];
    const float* b2    = (const float*)d_in[16];
    const float* bn3_g = (const float*)d_in[17];
    const float* bn3_b = (const float*)d_in[18];
    const float* w3    = (const float*)d_in[19];
    const float* b3    = (const float*)d_in[20];

    float *big, *act, *qkv;
    cudaGetSymbolAddress((void**)&big, g_big);
    cudaGetSymbolAddress((void**)&act, g_act);
    cudaGetSymbolAddress((void**)&qkv, g_qkv);

    dim3 ggrid(TTOK / 128, 4);   // 288 x 4 = 1152 blocks per GEMM

    // x -> channel-major
    transpose_in_kernel<<<dim3(16, 128), 288>>>(x);

    // ---- stage 1: o3 = conv(relu(bn1(x))) ----
    stats_kernel<<<512, 256>>>(0);
    scaleshift_kernel<<<2, 256>>>(bn1_g, bn1_b, 512);
    gemm_kernel<true,  false><<<ggrid, 256>>>(big, w1, b1, act, 512);

    // ---- MHSA(o3) ----
    gemm_kernel<false, false><<<ggrid, 256>>>(act, q_w, q_b, qkv,                      512);
    gemm_kernel<false, false><<<ggrid, 256>>>(act, k_w, k_b, qkv + (size_t)512 * TTOK, 512);
    gemm_kernel<false, false><<<ggrid, 256>>>(act, v_w, v_b, qkv + (size_t)1024 * TTOK, 512);
    attn_kernel<<<4096 * 4, 128>>>(rel_h, rel_w, 512);       // -> big rows [512,1024)

    // ---- stage 2: o7 = conv(relu(bn2(concat[x, o3_att]))) ----
    stats_kernel<<<512, 256>>>(512);
    scaleshift_kernel<<<4, 256>>>(bn2_g, bn2_b, 1024);
    gemm_kernel<true,  false><<<ggrid, 256>>>(big, w2, b2, act, 1024);

    // ---- MHSA(o7) ----
    gemm_kernel<false, false><<<ggrid, 256>>>(act, q_w, q_b, qkv,                      512);
    gemm_kernel<false, false><<<ggrid, 256>>>(act, k_w, k_b, qkv + (size_t)512 * TTOK, 512);
    gemm_kernel<false, false><<<ggrid, 256>>>(act, v_w, v_b, qkv + (size_t)1024 * TTOK, 512);
    attn_kernel<<<4096 * 4, 128>>>(rel_h, rel_w, 1024);      // -> big rows [1024,1536)

    // ---- stage 3: out = conv(relu(bn3(concat[x, o3_att, o7_att]))) ----
    stats_kernel<<<512, 256>>>(1024);
    scaleshift_kernel<<<6, 256>>>(bn3_g, bn3_b, 1536);
    gemm_kernel<true,  true ><<<ggrid, 256>>>(big, w3, b3, (float*)d_out, 1536);
}